// round 10
// baseline (speedup 1.0000x reference)
#include <cuda_runtime.h>
#include <cuda_bf16.h>
#include <cstdint>

// GRU seq2seq forecaster — fused tensor-core recurrence, two-tile pipelined.
//  K0: xsplit — pre-split x into bf16 hi/lo records [t][b]{32 hi, 32 lo}.
//  K1: CTA = 128 threads (4 warps). Each warp: n-quad wq, TWO independent
//      16-row tiles per step, sequenced MMA_A, MMA_B, epi_A, epi_B so the
//      gate epilogue overlaps the tensor pipe's execution of tile B.

#define B_    4096
#define TIN   168
#define C_    32
#define H_    64
#define TOUT  24

typedef uint32_t u32;

__device__ __nv_bfloat16 g_xs[(size_t)TIN * B_ * 64];   // 88 MB pre-split x

__device__ __forceinline__ float fsig(float a) {
    return __fdividef(1.0f, 1.0f + __expf(-a));
}
__device__ __forceinline__ float ftanh(float a) {
    float e = __expf(2.0f * a);
    return 1.0f - __fdividef(2.0f, e + 1.0f);
}
__device__ __forceinline__ void split2(float a, float b, u32& hi2, u32& lo2) {
    __nv_bfloat16 ah = __float2bfloat16(a), bh = __float2bfloat16(b);
    __nv_bfloat16 al = __float2bfloat16(a - __bfloat162float(ah));
    __nv_bfloat16 bl = __float2bfloat16(b - __bfloat162float(bh));
    hi2 = ((u32)__bfloat16_as_ushort(bh) << 16) | __bfloat16_as_ushort(ah);
    lo2 = ((u32)__bfloat16_as_ushort(bl) << 16) | __bfloat16_as_ushort(al);
}
__device__ __forceinline__ void MMA(float acc[4], u32 a0, u32 a1, u32 a2, u32 a3,
                                    u32 b0, u32 b1) {
    asm volatile(
        "mma.sync.aligned.m16n8k16.row.col.f32.bf16.bf16.f32 "
        "{%0,%1,%2,%3}, {%4,%5,%6,%7}, {%8,%9}, {%0,%1,%2,%3};"
        : "+f"(acc[0]), "+f"(acc[1]), "+f"(acc[2]), "+f"(acc[3])
        : "r"(a0), "r"(a1), "r"(a2), "r"(a3), "r"(b0), "r"(b1));
}
__device__ __forceinline__ u32 smem_u32(const void* p) {
    u32 a;
    asm("{ .reg .u64 t; cvta.to.shared.u64 t, %1; cvt.u32.u64 %0, t; }" : "=r"(a) : "l"(p));
    return a;
}
__device__ __forceinline__ void cp16(u32 daddr, const void* gsrc) {
    asm volatile("cp.async.cg.shared.global [%0], [%1], 16;"
                 :: "r"(daddr), "l"(gsrc) : "memory");
}

// ============================ kernel 0: x pre-split ============================
__global__ __launch_bounds__(256)
void xsplit_kernel(const float* __restrict__ x)
{
    const int p    = blockIdx.x * 128 + (threadIdx.x >> 1);
    const int half = threadIdx.x & 1;
    const int t = p >> 12, b = p & (B_ - 1);
    const float4* src = reinterpret_cast<const float4*>(x + ((size_t)b * TIN + t) * C_ + 16 * half);
    u32 hw[8], lw[8];
#pragma unroll
    for (int q = 0; q < 4; q++) {
        float4 v = src[q];
        split2(v.x, v.y, hw[2*q],   lw[2*q]);
        split2(v.z, v.w, hw[2*q+1], lw[2*q+1]);
    }
    char* dst = reinterpret_cast<char*>(g_xs) + (size_t)p * 128;
    *reinterpret_cast<uint4*>(dst + 32*half)           = make_uint4(hw[0],hw[1],hw[2],hw[3]);
    *reinterpret_cast<uint4*>(dst + 32*half + 16)      = make_uint4(hw[4],hw[5],hw[6],hw[7]);
    *reinterpret_cast<uint4*>(dst + 64 + 32*half)      = make_uint4(lw[0],lw[1],lw[2],lw[3]);
    *reinterpret_cast<uint4*>(dst + 64 + 32*half + 16) = make_uint4(lw[4],lw[5],lw[6],lw[7]);
}

// ============================ kernel 1: fused recurrence ============================
#define HS  136
#define PS  72
#define XSTR 36

#define OFF_H   0                        // [2][32][HS] bf16 = 17408
#define OFF_P   17408                    // [2][32][PS] bf16 =  9216
#define OFF_X   26624                    // [2][32 rows][144B] = 9216
#define OFF_WF  35840                    // [4][6][2][32] uint4 = 24576
#define OFF_PF  60416                    // [4][4][32] uint4 = 8192
#define SM_TOTAL 68608

__device__ __forceinline__ int permrow(int ln, int wq) {
    return (ln >> 4) * 64 + 16 * wq + (ln & 15);
}
__device__ __forceinline__ void load_wfrags(const float* __restrict__ W, int wq, int g, int tg,
                                            u32 (&bh)[6][4][2], u32 (&bl)[6][4][2]) {
#pragma unroll
    for (int nt = 0; nt < 6; nt++) {
        const float* row = W + permrow(nt * 8 + g, wq) * 64;
#pragma unroll
        for (int ks = 0; ks < 4; ks++) {
            const int k0 = ks * 16 + 2 * tg;
            split2(row[k0],     row[k0 + 1], bh[nt][ks][0], bl[nt][ks][0]);
            split2(row[k0 + 8], row[k0 + 9], bh[nt][ks][1], bl[nt][ks][1]);
        }
    }
}
#define LD_AFRAGS(dsth, dstl, base, S, r0_, r1_, tg_)                                   \
    _Pragma("unroll")                                                                    \
    for (int ks = 0; ks < 4; ks++) {                                                     \
        const int c0 = ks * 16 + 2 * (tg_);                                              \
        dsth[ks][0] = *reinterpret_cast<const u32*>(&(base)[(r0_) * (S) + c0]);          \
        dsth[ks][1] = *reinterpret_cast<const u32*>(&(base)[(r1_) * (S) + c0]);          \
        dsth[ks][2] = *reinterpret_cast<const u32*>(&(base)[(r0_) * (S) + c0 + 8]);      \
        dsth[ks][3] = *reinterpret_cast<const u32*>(&(base)[(r1_) * (S) + c0 + 8]);      \
        dstl[ks][0] = *reinterpret_cast<const u32*>(&(base)[(r0_) * (S) + 64 + c0]);     \
        dstl[ks][1] = *reinterpret_cast<const u32*>(&(base)[(r1_) * (S) + 64 + c0]);     \
        dstl[ks][2] = *reinterpret_cast<const u32*>(&(base)[(r0_) * (S) + 64 + c0 + 8]); \
        dstl[ks][3] = *reinterpret_cast<const u32*>(&(base)[(r1_) * (S) + 64 + c0 + 8]); \
    }

// h@Whh (regs) + x@Wih (smem frag-major) for one 16-row tile.
__device__ __forceinline__ void mma_hx(
    const __nv_bfloat16* hb, int r0, int r1, int tg, int lane,
    const u32 (&bh)[6][4][2], const u32 (&bl)[6][4][2],
    const u32 (&xh)[2][4], const u32 (&xl)[2][4],
    const uint4* sWfq,
    float (&accW)[6][4], float (&accP)[2][4])
{
    u32 ah4[4][4], al4[4][4];
    LD_AFRAGS(ah4, al4, hb, HS, r0, r1, tg);
#pragma unroll
    for (int q = 0; q < 2; q++) { accP[q][0]=0.f; accP[q][1]=0.f; accP[q][2]=0.f; accP[q][3]=0.f; }
#pragma unroll
    for (int nt = 0; nt < 6; nt++) {
        float* A = accW[nt];
        A[0]=0.f; A[1]=0.f; A[2]=0.f; A[3]=0.f;
#pragma unroll
        for (int ks = 0; ks < 4; ks++)
            MMA(A, ah4[ks][0], ah4[ks][1], ah4[ks][2], ah4[ks][3], bh[nt][ks][0], bh[nt][ks][1]);
#pragma unroll
        for (int ks = 0; ks < 4; ks++)
            MMA(A, al4[ks][0], al4[ks][1], al4[ks][2], al4[ks][3], bh[nt][ks][0], bh[nt][ks][1]);
#pragma unroll
        for (int ks = 0; ks < 4; ks++)
            MMA(A, ah4[ks][0], ah4[ks][1], ah4[ks][2], ah4[ks][3], bl[nt][ks][0], bl[nt][ks][1]);
        float* T = (nt < 4) ? A : accP[nt - 4];
#pragma unroll
        for (int ks = 0; ks < 2; ks++) {
            const uint4 w = sWfq[(nt * 2 + ks) * 32 + lane];
            MMA(T, xh[ks][0], xh[ks][1], xh[ks][2], xh[ks][3], w.x, w.y);
            MMA(T, xl[ks][0], xl[ks][1], xl[ks][2], xl[ks][3], w.x, w.y);
            MMA(T, xh[ks][0], xh[ks][1], xh[ks][2], xh[ks][3], w.z, w.w);
        }
    }
}

// gates + h update + split-store for one tile (8 elements of this lane).
__device__ __forceinline__ void gates_update(
    const float (&accW)[6][4], const float (&accP)[2][4],
    const float (&br)[4], const float (&bz)[4], const float (&ni)[4], const float (&nh)[4],
    float (&h)[8], __nv_bfloat16* hw, int r0, int r1, int wq, int tg)
{
#pragma unroll
    for (int rh = 0; rh < 2; rh++) {
#pragma unroll
        for (int s = 0; s < 2; s++) {
            const int e = rh * 4 + s * 2;
            const float rg0 = fsig(accW[s][2*rh]   + br[s*2]);
            const float rg1 = fsig(accW[s][2*rh+1] + br[s*2+1]);
            const float z0  = fsig(accW[2+s][2*rh]   + bz[s*2]);
            const float z1  = fsig(accW[2+s][2*rh+1] + bz[s*2+1]);
            const float n0  = ftanh(accP[s][2*rh]   + ni[s*2]   + rg0 * (accW[4+s][2*rh]   + nh[s*2]));
            const float n1  = ftanh(accP[s][2*rh+1] + ni[s*2+1] + rg1 * (accW[4+s][2*rh+1] + nh[s*2+1]));
            h[e]   = (1.0f - z0) * n0 + z0 * h[e];
            h[e+1] = (1.0f - z1) * n1 + z1 * h[e+1];
            u32 vh, vl; split2(h[e], h[e+1], vh, vl);
            const int row = rh ? r1 : r0;
            const int col = 16 * wq + s * 8 + 2 * tg;
            *reinterpret_cast<u32*>(&hw[row * HS + col])      = vh;
            *reinterpret_cast<u32*>(&hw[row * HS + 64 + col]) = vl;
        }
    }
}

__device__ __forceinline__ void ld_xfrags(const u32* xb, int r0, int r1, int tg,
                                          u32 (&xh)[2][4], u32 (&xl)[2][4])
{
#pragma unroll
    for (int ks = 0; ks < 2; ks++) {
        const int i0 = r0 * XSTR + 8 * ks + tg, i1 = r1 * XSTR + 8 * ks + tg;
        xh[ks][0] = xb[i0];      xh[ks][1] = xb[i1];
        xh[ks][2] = xb[i0 + 4];  xh[ks][3] = xb[i1 + 4];
        xl[ks][0] = xb[i0 + 16]; xl[ks][1] = xb[i1 + 16];
        xl[ks][2] = xb[i0 + 20]; xl[ks][3] = xb[i1 + 20];
    }
}
__device__ __forceinline__ void ld_pfrags(const __nv_bfloat16* pbuf, int r0, int r1, int tg,
                                          u32 (&aph)[2][4], u32 (&apl)[2][4])
{
#pragma unroll
    for (int ks = 0; ks < 2; ks++) {
        const int c0 = ks * 16 + 2 * tg;
        aph[ks][0] = *reinterpret_cast<const u32*>(&pbuf[r0 * PS + c0]);
        aph[ks][1] = *reinterpret_cast<const u32*>(&pbuf[r1 * PS + c0]);
        aph[ks][2] = *reinterpret_cast<const u32*>(&pbuf[r0 * PS + c0 + 8]);
        aph[ks][3] = *reinterpret_cast<const u32*>(&pbuf[r1 * PS + c0 + 8]);
        apl[ks][0] = *reinterpret_cast<const u32*>(&pbuf[r0 * PS + 32 + c0]);
        apl[ks][1] = *reinterpret_cast<const u32*>(&pbuf[r1 * PS + 32 + c0]);
        apl[ks][2] = *reinterpret_cast<const u32*>(&pbuf[r0 * PS + 32 + c0 + 8]);
        apl[ks][3] = *reinterpret_cast<const u32*>(&pbuf[r1 * PS + 32 + c0 + 8]);
    }
}
__device__ __forceinline__ void proj_tile(
    const __nv_bfloat16* hn, int r0, int r1, int tg, int wq, int lane,
    const uint4* sPf, float pb0, float pb1,
    float* __restrict__ out, int growA, int growB, int t, __nv_bfloat16* pn)
{
    u32 nh4[4][4], nl4[4][4];
    LD_AFRAGS(nh4, nl4, hn, HS, r0, r1, tg);
    float pacc[4] = {0.f, 0.f, 0.f, 0.f};
#pragma unroll
    for (int ks = 0; ks < 4; ks++) {
        const uint4 w = sPf[(wq * 4 + ks) * 32 + lane];
        MMA(pacc, nh4[ks][0], nh4[ks][1], nh4[ks][2], nh4[ks][3], w.x, w.y);
        MMA(pacc, nl4[ks][0], nl4[ks][1], nl4[ks][2], nl4[ks][3], w.x, w.y);
        MMA(pacc, nh4[ks][0], nh4[ks][1], nh4[ks][2], nh4[ks][3], w.z, w.w);
    }
    const float p00 = pacc[0] + pb0, p01 = pacc[1] + pb1;
    const float p10 = pacc[2] + pb0, p11 = pacc[3] + pb1;
    const int col = 8 * wq + 2 * tg;
    *reinterpret_cast<float2*>(&out[((size_t)growA * TOUT + t) * C_ + col]) = make_float2(p00, p01);
    *reinterpret_cast<float2*>(&out[((size_t)growB * TOUT + t) * C_ + col]) = make_float2(p10, p11);
    u32 vh, vl;
    split2(p00, p01, vh, vl);
    *reinterpret_cast<u32*>(&pn[r0 * PS + col])      = vh;
    *reinterpret_cast<u32*>(&pn[r0 * PS + 32 + col]) = vl;
    split2(p10, p11, vh, vl);
    *reinterpret_cast<u32*>(&pn[r1 * PS + col])      = vh;
    *reinterpret_cast<u32*>(&pn[r1 * PS + 32 + col]) = vl;
}

__global__ __launch_bounds__(128)
void gru_fused(const float* __restrict__ x,
               const float* __restrict__ eWih, const float* __restrict__ eWhh,
               const float* __restrict__ eBih, const float* __restrict__ eBhh,
               const float* __restrict__ dWih, const float* __restrict__ dWhh,
               const float* __restrict__ dBih, const float* __restrict__ dBhh,
               const float* __restrict__ pW,   const float* __restrict__ pB,
               float* __restrict__ out)
{
    extern __shared__ __align__(16) char smem[];
    __nv_bfloat16* sH = reinterpret_cast<__nv_bfloat16*>(smem + OFF_H);
    __nv_bfloat16* sP = reinterpret_cast<__nv_bfloat16*>(smem + OFF_P);
    const u32* sX     = reinterpret_cast<const u32*>(smem + OFF_X);
    uint4* sWf        = reinterpret_cast<uint4*>(smem + OFF_WF);
    uint4* sPf        = reinterpret_cast<uint4*>(smem + OFF_PF);
    const u32 smb = smem_u32(smem);

    const int tid  = threadIdx.x;
    const int wq   = tid >> 5;         // 0..3 (4 warps)
    const int lane = tid & 31;
    const int g  = lane >> 2;
    const int tg = lane & 3;
    const int r0 = g, r1 = g + 8;      // tile0 rows; tile1 adds +16
    const int rowbase = blockIdx.x * 32;
    const int ldrow = tid >> 2, c2 = (tid & 3) * 2;   // cp.async: 2 chunks/thread
    const uint4* sWfq = sWf + wq * 384;

    // ---- init: zero h buffers; stage encoder Wih frags (each warp its wq) ----
    for (int i = tid; i < 2 * 32 * HS; i += 128)
        reinterpret_cast<unsigned short*>(sH)[i] = 0;
#pragma unroll
    for (int nt = 0; nt < 6; nt++)
#pragma unroll
        for (int ks = 0; ks < 2; ks++) {
            const float* wr = eWih + permrow(nt * 8 + g, wq) * 32 + ks * 16 + 2 * tg;
            u32 h0, l0, h1, l1;
            split2(wr[0], wr[1], h0, l0);
            split2(wr[8], wr[9], h1, l1);
            sWf[((wq * 6 + nt) * 2 + ks) * 32 + lane] = make_uint4(h0, h1, l0, l1);
        }
    u32 bh[6][4][2], bl[6][4][2];
    load_wfrags(eWhh, wq, g, tg, bh, bl);
    float ebr[4], ebz[4], eni[4], enh[4];
#pragma unroll
    for (int sp = 0; sp < 4; sp++) {
        const int u = 16 * wq + (sp >> 1) * 8 + 2 * tg + (sp & 1);
        ebr[sp] = eBih[u] + eBhh[u];
        ebz[sp] = eBih[64 + u] + eBhh[64 + u];
        eni[sp] = eBih[128 + u];
        enh[sp] = eBhh[128 + u];
    }
    __syncthreads();

    {   // prologue: prefetch x tile t=0 (32 rows x 128B)
        const char* src = reinterpret_cast<const char*>(g_xs)
                        + ((size_t)(rowbase + ldrow)) * 128 + c2 * 16;
        const u32 d = smb + OFF_X + ldrow * 144 + c2 * 16;
        cp16(d, src); cp16(d + 16, src + 16);
        asm volatile("cp.async.commit_group;" ::: "memory");
    }

    float h0[8], h1[8];
#pragma unroll
    for (int e = 0; e < 8; e++) { h0[e] = 0.0f; h1[e] = 0.0f; }
    int hp = 0;

    // ======================= encoder: 168 steps =======================
    for (int t = 0; t < TIN; t++) {
        asm volatile("cp.async.wait_group 0;" ::: "memory");
        __syncthreads();
        if (t + 1 < TIN) {
            const char* src = reinterpret_cast<const char*>(g_xs)
                            + ((size_t)(t + 1) * B_ + rowbase + ldrow) * 128 + c2 * 16;
            const u32 d = smb + OFF_X + ((t + 1) & 1) * 4608 + ldrow * 144 + c2 * 16;
            cp16(d, src); cp16(d + 16, src + 16);
            asm volatile("cp.async.commit_group;" ::: "memory");
        }

        const __nv_bfloat16* hb = sH + hp * 32 * HS;
        const u32* xb = sX + (t & 1) * 1152;

        // tile A (rows 0..15)
        u32 xhA[2][4], xlA[2][4];
        ld_xfrags(xb, r0, r1, tg, xhA, xlA);
        float accW0[6][4], accP0[2][4];
        mma_hx(hb, r0, r1, tg, lane, bh, bl, xhA, xlA, sWfq, accW0, accP0);

        // tile B (rows 16..31) — issues while A's MMAs drain
        u32 xhB[2][4], xlB[2][4];
        ld_xfrags(xb, r0 + 16, r1 + 16, tg, xhB, xlB);
        float accW1[6][4], accP1[2][4];
        mma_hx(hb, r0 + 16, r1 + 16, tg, lane, bh, bl, xhB, xlB, sWfq, accW1, accP1);

        // epi A overlaps tile B tensor execution; epi B is the tail
        __nv_bfloat16* hw = sH + (hp ^ 1) * 32 * HS;
        gates_update(accW0, accP0, ebr, ebz, eni, enh, h0, hw, r0, r1, wq, tg);
        gates_update(accW1, accP1, ebr, ebz, eni, enh, h1, hw, r0 + 16, r1 + 16, wq, tg);
        hp ^= 1;
    }

    // ======================= decoder: 24 steps =======================
    __syncthreads();
    // restage frag-major: decoder Wih + projection W (each warp its wq)
#pragma unroll
    for (int nt = 0; nt < 6; nt++)
#pragma unroll
        for (int ks = 0; ks < 2; ks++) {
            const float* wr = dWih + permrow(nt * 8 + g, wq) * 32 + ks * 16 + 2 * tg;
            u32 h0f, l0f, h1f, l1f;
            split2(wr[0], wr[1], h0f, l0f);
            split2(wr[8], wr[9], h1f, l1f);
            sWf[((wq * 6 + nt) * 2 + ks) * 32 + lane] = make_uint4(h0f, h1f, l0f, l1f);
        }
#pragma unroll
    for (int ks = 0; ks < 4; ks++) {
        const float* wr = pW + (8 * wq + g) * 64 + ks * 16 + 2 * tg;
        u32 h0f, l0f, h1f, l1f;
        split2(wr[0], wr[1], h0f, l0f);
        split2(wr[8], wr[9], h1f, l1f);
        sPf[(wq * 4 + ks) * 32 + lane] = make_uint4(h0f, h1f, l0f, l1f);
    }
    load_wfrags(dWhh, wq, g, tg, bh, bl);
    float dbr[4], dbz[4], dni[4], dnh[4];
#pragma unroll
    for (int sp = 0; sp < 4; sp++) {
        const int u = 16 * wq + (sp >> 1) * 8 + 2 * tg + (sp & 1);
        dbr[sp] = dBih[u] + dBhh[u];
        dbz[sp] = dBih[64 + u] + dBhh[64 + u];
        dni[sp] = dBih[128 + u];
        dnh[sp] = dBhh[128 + u];
    }
    const float pb0 = pB[8 * wq + 2 * tg], pb1 = pB[8 * wq + 2 * tg + 1];

    for (int i = tid; i < 32 * 32; i += 128) {   // prev_0 = x[:, TIN-1, :]
        const int rw = i >> 5, c = i & 31;
        const float v = x[((size_t)(rowbase + rw) * TIN + (TIN - 1)) * C_ + c];
        const __nv_bfloat16 hi = __float2bfloat16(v);
        sP[rw * PS + c]      = hi;
        sP[rw * PS + 32 + c] = __float2bfloat16(v - __bfloat162float(hi));
    }
    __syncthreads();

    int pp = 0;
    for (int t = 0; t < TOUT; t++) {
        const __nv_bfloat16* hb = sH + hp * 32 * HS;
        const __nv_bfloat16* pbuf = sP + pp * 32 * PS;

        u32 aphA[2][4], aplA[2][4];
        ld_pfrags(pbuf, r0, r1, tg, aphA, aplA);
        float accW0[6][4], accP0[2][4];
        mma_hx(hb, r0, r1, tg, lane, bh, bl, aphA, aplA, sWfq, accW0, accP0);

        u32 aphB[2][4], aplB[2][4];
        ld_pfrags(pbuf, r0 + 16, r1 + 16, tg, aphB, aplB);
        float accW1[6][4], accP1[2][4];
        mma_hx(hb, r0 + 16, r1 + 16, tg, lane, bh, bl, aphB, aplB, sWfq, accW1, accP1);

        __nv_bfloat16* hw = sH + (hp ^ 1) * 32 * HS;
        gates_update(accW0, accP0, dbr, dbz, dni, dnh, h0, hw, r0, r1, wq, tg);
        gates_update(accW1, accP1, dbr, dbz, dni, dnh, h1, hw, r0 + 16, r1 + 16, wq, tg);
        __syncthreads();

        // projection from NEW h (needs all wq columns -> after barrier)
        const __nv_bfloat16* hn = sH + (hp ^ 1) * 32 * HS;
        __nv_bfloat16* pn = sP + (pp ^ 1) * 32 * PS;
        proj_tile(hn, r0, r1, tg, wq, lane, sPf, pb0, pb1,
                  out, rowbase + r0, rowbase + r1, t, pn);
        proj_tile(hn, r0 + 16, r1 + 16, tg, wq, lane, sPf, pb0, pb1,
                  out, rowbase + r0 + 16, rowbase + r1 + 16, t, pn);
        __syncthreads();
        hp ^= 1; pp ^= 1;
    }
}

// ============================ launch ============================
extern "C" void kernel_launch(void* const* d_in, const int* in_sizes, int n_in,
                              void* d_out, int out_size)
{
    (void)in_sizes; (void)n_in; (void)out_size;
    const float* x    = (const float*)d_in[0];
    const float* eWih = (const float*)d_in[1];
    const float* eWhh = (const float*)d_in[2];
    const float* eBih = (const float*)d_in[3];
    const float* eBhh = (const float*)d_in[4];
    const float* dWih = (const float*)d_in[5];
    const float* dWhh = (const float*)d_in[6];
    const float* dBih = (const float*)d_in[7];
    const float* dBhh = (const float*)d_in[8];
    const float* pW   = (const float*)d_in[9];
    const float* pB   = (const float*)d_in[10];
    float* out = (float*)d_out;

    xsplit_kernel<<<(TIN * B_) / 128, 256>>>(x);

    cudaFuncSetAttribute(gru_fused,
                         cudaFuncAttributeMaxDynamicSharedMemorySize, SM_TOTAL);
    gru_fused<<<B_ / 32, 128, SM_TOTAL>>>(
        x, eWih, eWhh, eBih, eBhh, dWih, dWhh, dBih, dBhh, pW, pB, out);
}

// round 11
// speedup vs baseline: 1.0703x; 1.0703x over previous
#include <cuda_runtime.h>
#include <cuda_bf16.h>
#include <cstdint>

// GRU seq2seq forecaster — fused tensor-core recurrence, 16 warps / 512 threads.
//  K0: xsplit — pre-split x into bf16 hi/lo records [t][b]{32 hi, 32 lo}.
//  K1: warp = (mh row-half, wn unit-octet). Per warp: 24 output cols (r,z,n of
//      8 units), 54 MMA/step. 4 warps/SMSP hide each other's gate epilogues.
//      Whh hi frags in regs, lo frags in SMEM (reg cap 128 @ 512 threads).

#define B_    4096
#define TIN   168
#define C_    32
#define H_    64
#define TOUT  24

typedef uint32_t u32;

__device__ __nv_bfloat16 g_xs[(size_t)TIN * B_ * 64];   // 88 MB pre-split x

__device__ __forceinline__ float fsig(float a) {
    return __fdividef(1.0f, 1.0f + __expf(-a));
}
__device__ __forceinline__ float ftanh(float a) {
    float e = __expf(2.0f * a);
    return 1.0f - __fdividef(2.0f, e + 1.0f);
}
// packed split: hi2 = (bf16(b)<<16)|bf16(a), lo2 = residuals (same layout)
__device__ __forceinline__ void split2(float a, float b, u32& hi2, u32& lo2) {
    asm("cvt.rn.bf16x2.f32 %0, %1, %2;" : "=r"(hi2) : "f"(b), "f"(a));
    const float ah = __uint_as_float(hi2 << 16);
    const float bh = __uint_as_float(hi2 & 0xFFFF0000u);
    asm("cvt.rn.bf16x2.f32 %0, %1, %2;" : "=r"(lo2) : "f"(b - bh), "f"(a - ah));
}
__device__ __forceinline__ void MMA(float acc[4], u32 a0, u32 a1, u32 a2, u32 a3,
                                    u32 b0, u32 b1) {
    asm volatile(
        "mma.sync.aligned.m16n8k16.row.col.f32.bf16.bf16.f32 "
        "{%0,%1,%2,%3}, {%4,%5,%6,%7}, {%8,%9}, {%0,%1,%2,%3};"
        : "+f"(acc[0]), "+f"(acc[1]), "+f"(acc[2]), "+f"(acc[3])
        : "r"(a0), "r"(a1), "r"(a2), "r"(a3), "r"(b0), "r"(b1));
}
__device__ __forceinline__ u32 smem_u32(const void* p) {
    u32 a;
    asm("{ .reg .u64 t; cvta.to.shared.u64 t, %1; cvt.u32.u64 %0, t; }" : "=r"(a) : "l"(p));
    return a;
}
__device__ __forceinline__ void cp16(u32 daddr, const void* gsrc) {
    asm volatile("cp.async.cg.shared.global [%0], [%1], 16;"
                 :: "r"(daddr), "l"(gsrc) : "memory");
}

// ============================ kernel 0: x pre-split ============================
__global__ __launch_bounds__(256)
void xsplit_kernel(const float* __restrict__ x)
{
    const int p    = blockIdx.x * 128 + (threadIdx.x >> 1);
    const int half = threadIdx.x & 1;
    const int t = p >> 12, b = p & (B_ - 1);
    const float4* src = reinterpret_cast<const float4*>(x + ((size_t)b * TIN + t) * C_ + 16 * half);
    u32 hw[8], lw[8];
#pragma unroll
    for (int q = 0; q < 4; q++) {
        float4 v = src[q];
        split2(v.x, v.y, hw[2*q],   lw[2*q]);
        split2(v.z, v.w, hw[2*q+1], lw[2*q+1]);
    }
    char* dst = reinterpret_cast<char*>(g_xs) + (size_t)p * 128;
    *reinterpret_cast<uint4*>(dst + 32*half)           = make_uint4(hw[0],hw[1],hw[2],hw[3]);
    *reinterpret_cast<uint4*>(dst + 32*half + 16)      = make_uint4(hw[4],hw[5],hw[6],hw[7]);
    *reinterpret_cast<uint4*>(dst + 64 + 32*half)      = make_uint4(lw[0],lw[1],lw[2],lw[3]);
    *reinterpret_cast<uint4*>(dst + 64 + 32*half + 16) = make_uint4(lw[4],lw[5],lw[6],lw[7]);
}

// ============================ kernel 1: fused recurrence ============================
#define HS   136     // sH row stride (bf16): 64 hi + 64 lo + 8 pad
#define PS   72      // sP row stride (bf16): 32 hi + 32 lo + 8 pad
#define XSTR 36      // x tile row stride (u32): 32 data + 4 pad (144B)

#define OFF_H   0                         // [2 par][32][HS] bf16     = 17408
#define OFF_P   17408                     // [2 par][32][PS] bf16     =  9216
#define OFF_X   26624                     // [2 grp][2 buf][16][144B] =  9216
#define OFF_WF  35840                     // [8 wn][3 nt][2 ks][32] uint4 = 24576
#define OFF_PF  60416                     // [4 cb][4 ks][32] uint4   =  8192
#define OFF_WL  68608                     // [8 wn][3 nt][4 ks][32] uint2 = 24576
#define SM_TOTAL 93184

#define LD_AFRAGS(dsth, dstl, base, S, r0_, r1_, tg_)                                   \
    _Pragma("unroll")                                                                    \
    for (int ks = 0; ks < 4; ks++) {                                                     \
        const int c0 = ks * 16 + 2 * (tg_);                                              \
        dsth[ks][0] = *reinterpret_cast<const u32*>(&(base)[(r0_) * (S) + c0]);          \
        dsth[ks][1] = *reinterpret_cast<const u32*>(&(base)[(r1_) * (S) + c0]);          \
        dsth[ks][2] = *reinterpret_cast<const u32*>(&(base)[(r0_) * (S) + c0 + 8]);      \
        dsth[ks][3] = *reinterpret_cast<const u32*>(&(base)[(r1_) * (S) + c0 + 8]);      \
        dstl[ks][0] = *reinterpret_cast<const u32*>(&(base)[(r0_) * (S) + 64 + c0]);     \
        dstl[ks][1] = *reinterpret_cast<const u32*>(&(base)[(r1_) * (S) + 64 + c0]);     \
        dstl[ks][2] = *reinterpret_cast<const u32*>(&(base)[(r0_) * (S) + 64 + c0 + 8]); \
        dstl[ks][3] = *reinterpret_cast<const u32*>(&(base)[(r1_) * (S) + 64 + c0 + 8]); \
    }

__global__ __launch_bounds__(512, 1)
void gru_fused(const float* __restrict__ x,
               const float* __restrict__ eWih, const float* __restrict__ eWhh,
               const float* __restrict__ eBih, const float* __restrict__ eBhh,
               const float* __restrict__ dWih, const float* __restrict__ dWhh,
               const float* __restrict__ dBih, const float* __restrict__ dBhh,
               const float* __restrict__ pW,   const float* __restrict__ pB,
               float* __restrict__ out)
{
    extern __shared__ __align__(16) char smem[];
    __nv_bfloat16* sH = reinterpret_cast<__nv_bfloat16*>(smem + OFF_H);
    __nv_bfloat16* sP = reinterpret_cast<__nv_bfloat16*>(smem + OFF_P);
    const u32* sX     = reinterpret_cast<const u32*>(smem + OFF_X);
    uint4* sWf        = reinterpret_cast<uint4*>(smem + OFF_WF);
    uint4* sPf        = reinterpret_cast<uint4*>(smem + OFF_PF);
    uint2* sWl        = reinterpret_cast<uint2*>(smem + OFF_WL);
    const u32 smb = smem_u32(smem);

    const int tid  = threadIdx.x;
    const int wid  = tid >> 5;
    const int lane = tid & 31;
    const int g  = lane >> 2;
    const int tg = lane & 3;
    const int mh = wid >> 3;           // row-half (0,1)
    const int wn = wid & 7;            // unit octet (0..7)
    const int R0 = mh * 16 + g, R1 = R0 + 8;
    const int rowbase = blockIdx.x * 32;
    const int barid = 1 + mh;
    const int g256 = tid & 255;
    const int xgbase = OFF_X + mh * 4608;      // group-private x double buffer

    // ---- zero h buffers ----
    for (int i = tid; i < 2 * 32 * HS; i += 512)
        reinterpret_cast<unsigned short*>(sH)[i] = 0;

    // ---- stage encoder x-weights (frag-major), Whh hi->regs / lo->smem ----
    if (mh == 0) {
#pragma unroll
        for (int nt = 0; nt < 3; nt++)
#pragma unroll
            for (int ks = 0; ks < 2; ks++) {
                const float* wr = eWih + (nt * 64 + 8 * wn + g) * 32 + ks * 16 + 2 * tg;
                u32 h0, l0, h1, l1;
                split2(wr[0], wr[1], h0, l0);
                split2(wr[8], wr[9], h1, l1);
                sWf[((wn * 3 + nt) * 2 + ks) * 32 + lane] = make_uint4(h0, h1, l0, l1);
            }
    }
    u32 bh[3][4][2];
#pragma unroll
    for (int nt = 0; nt < 3; nt++)
#pragma unroll
        for (int ks = 0; ks < 4; ks++) {
            const float* wr = eWhh + (nt * 64 + 8 * wn + g) * 64 + ks * 16 + 2 * tg;
            u32 h0, l0, h1, l1;
            split2(wr[0], wr[1], h0, l0);
            split2(wr[8], wr[9], h1, l1);
            bh[nt][ks][0] = h0; bh[nt][ks][1] = h1;
            if (mh == 0) sWl[((wn * 3 + nt) * 4 + ks) * 32 + lane] = make_uint2(l0, l1);
        }
    const int u0 = 8 * wn + 2 * tg;
    float br[2], bz[2], ni[2], nh[2];
#pragma unroll
    for (int c = 0; c < 2; c++) {
        br[c] = eBih[u0 + c] + eBhh[u0 + c];
        bz[c] = eBih[64 + u0 + c] + eBhh[64 + u0 + c];
        ni[c] = eBih[128 + u0 + c];
        nh[c] = eBhh[128 + u0 + c];
    }
    __syncthreads();

    // prologue: prefetch own group's x tile t=0 (16 rows x 128B)
    if (g256 < 128) {
        const int rl = g256 >> 3, ch = g256 & 7;
        const char* src = reinterpret_cast<const char*>(g_xs)
                        + ((size_t)(rowbase + mh * 16 + rl)) * 128 + ch * 16;
        cp16(smb + xgbase + rl * 144 + ch * 16, src);
        asm volatile("cp.async.commit_group;" ::: "memory");
    }

    float h[4];
#pragma unroll
    for (int j = 0; j < 4; j++) h[j] = 0.0f;
    int hp = 0;

    // ======================= encoder: 168 steps =======================
    for (int t = 0; t < TIN; t++) {
        asm volatile("cp.async.wait_group 0;" ::: "memory");
        asm volatile("bar.sync %0, %1;" :: "r"(barid), "r"(256) : "memory");
        if (t + 1 < TIN && g256 < 128) {
            const int rl = g256 >> 3, ch = g256 & 7;
            const char* src = reinterpret_cast<const char*>(g_xs)
                            + ((size_t)(t + 1) * B_ + rowbase + mh * 16 + rl) * 128 + ch * 16;
            cp16(smb + xgbase + ((t + 1) & 1) * 2304 + rl * 144 + ch * 16, src);
            asm volatile("cp.async.commit_group;" ::: "memory");
        }

        const __nv_bfloat16* hb = sH + hp * 32 * HS;
        u32 ah4[4][4], al4[4][4];
        LD_AFRAGS(ah4, al4, hb, HS, R0, R1, tg);
        const u32* xb = sX + mh * 1152 + (t & 1) * 576;
        u32 xh[2][4], xl[2][4];
#pragma unroll
        for (int ks = 0; ks < 2; ks++) {
            const int i0 = g * XSTR + 8 * ks + tg, i1 = (g + 8) * XSTR + 8 * ks + tg;
            xh[ks][0] = xb[i0];      xh[ks][1] = xb[i1];
            xh[ks][2] = xb[i0 + 4];  xh[ks][3] = xb[i1 + 4];
            xl[ks][0] = xb[i0 + 16]; xl[ks][1] = xb[i1 + 16];
            xl[ks][2] = xb[i0 + 20]; xl[ks][3] = xb[i1 + 20];
        }

        float accW[3][4], accP[4];
#pragma unroll
        for (int nt = 0; nt < 3; nt++) { accW[nt][0]=0.f; accW[nt][1]=0.f; accW[nt][2]=0.f; accW[nt][3]=0.f; }
        accP[0]=0.f; accP[1]=0.f; accP[2]=0.f; accP[3]=0.f;

        // h_hi @ W_hi
#pragma unroll
        for (int nt = 0; nt < 3; nt++)
#pragma unroll
            for (int ks = 0; ks < 4; ks++)
                MMA(accW[nt], ah4[ks][0], ah4[ks][1], ah4[ks][2], ah4[ks][3], bh[nt][ks][0], bh[nt][ks][1]);
        // x products (hi*Wh, lo*Wh, hi*Wl)
#pragma unroll
        for (int nt = 0; nt < 3; nt++) {
            float* T = (nt < 2) ? accW[nt] : accP;
#pragma unroll
            for (int ks = 0; ks < 2; ks++) {
                const uint4 w = sWf[((wn * 3 + nt) * 2 + ks) * 32 + lane];
                MMA(T, xh[ks][0], xh[ks][1], xh[ks][2], xh[ks][3], w.x, w.y);
                MMA(T, xl[ks][0], xl[ks][1], xl[ks][2], xl[ks][3], w.x, w.y);
                MMA(T, xh[ks][0], xh[ks][1], xh[ks][2], xh[ks][3], w.z, w.w);
            }
        }
        // h_lo @ W_hi
#pragma unroll
        for (int nt = 0; nt < 3; nt++)
#pragma unroll
            for (int ks = 0; ks < 4; ks++)
                MMA(accW[nt], al4[ks][0], al4[ks][1], al4[ks][2], al4[ks][3], bh[nt][ks][0], bh[nt][ks][1]);
        // h_hi @ W_lo (lo frags from smem)
#pragma unroll
        for (int nt = 0; nt < 3; nt++)
#pragma unroll
            for (int ks = 0; ks < 4; ks++) {
                const uint2 wl = sWl[((wn * 3 + nt) * 4 + ks) * 32 + lane];
                MMA(accW[nt], ah4[ks][0], ah4[ks][1], ah4[ks][2], ah4[ks][3], wl.x, wl.y);
            }

        // gates + h update + store
        __nv_bfloat16* hw = sH + (hp ^ 1) * 32 * HS;
#pragma unroll
        for (int j = 0; j < 4; j++) {
            const int c = j & 1;
            const float rg = fsig(accW[0][j] + br[c]);
            const float zg = fsig(accW[1][j] + bz[c]);
            const float nn = ftanh(accP[j] + ni[c] + rg * (accW[2][j] + nh[c]));
            h[j] = nn + zg * (h[j] - nn);
        }
        {
            const int col = 8 * wn + 2 * tg;
            u32 vh, vl;
            split2(h[0], h[1], vh, vl);
            *reinterpret_cast<u32*>(&hw[R0 * HS + col])      = vh;
            *reinterpret_cast<u32*>(&hw[R0 * HS + 64 + col]) = vl;
            split2(h[2], h[3], vh, vl);
            *reinterpret_cast<u32*>(&hw[R1 * HS + col])      = vh;
            *reinterpret_cast<u32*>(&hw[R1 * HS + 64 + col]) = vl;
        }
        hp ^= 1;
    }

    // ======================= decoder: 24 steps =======================
    __syncthreads();
    // restage: decoder x-weights, dWhh hi->regs / lo->smem, projection W
    if (mh == 0) {
#pragma unroll
        for (int nt = 0; nt < 3; nt++)
#pragma unroll
            for (int ks = 0; ks < 2; ks++) {
                const float* wr = dWih + (nt * 64 + 8 * wn + g) * 32 + ks * 16 + 2 * tg;
                u32 h0, l0, h1, l1;
                split2(wr[0], wr[1], h0, l0);
                split2(wr[8], wr[9], h1, l1);
                sWf[((wn * 3 + nt) * 2 + ks) * 32 + lane] = make_uint4(h0, h1, l0, l1);
            }
        if (wn < 4) {
#pragma unroll
            for (int ks = 0; ks < 4; ks++) {
                const float* wr = pW + (8 * wn + g) * 64 + ks * 16 + 2 * tg;
                u32 h0, l0, h1, l1;
                split2(wr[0], wr[1], h0, l0);
                split2(wr[8], wr[9], h1, l1);
                sPf[(wn * 4 + ks) * 32 + lane] = make_uint4(h0, h1, l0, l1);
            }
        }
    }
#pragma unroll
    for (int nt = 0; nt < 3; nt++)
#pragma unroll
        for (int ks = 0; ks < 4; ks++) {
            const float* wr = dWhh + (nt * 64 + 8 * wn + g) * 64 + ks * 16 + 2 * tg;
            u32 h0, l0, h1, l1;
            split2(wr[0], wr[1], h0, l0);
            split2(wr[8], wr[9], h1, l1);
            bh[nt][ks][0] = h0; bh[nt][ks][1] = h1;
            if (mh == 0) sWl[((wn * 3 + nt) * 4 + ks) * 32 + lane] = make_uint2(l0, l1);
        }
#pragma unroll
    for (int c = 0; c < 2; c++) {
        br[c] = dBih[u0 + c] + dBhh[u0 + c];
        bz[c] = dBih[64 + u0 + c] + dBhh[64 + u0 + c];
        ni[c] = dBih[128 + u0 + c];
        nh[c] = dBhh[128 + u0 + c];
    }
    const int pcol = 8 * (wn & 3) + 2 * tg;
    const float pb0 = pB[pcol], pb1 = pB[pcol + 1];

    // prev_0 = x[:, TIN-1, :] for own group's rows
    for (int i = g256; i < 16 * 32; i += 256) {
        const int rl = i >> 5, c = i & 31;
        const int rw = mh * 16 + rl;
        const float v = x[((size_t)(rowbase + rw) * TIN + (TIN - 1)) * C_ + c];
        const __nv_bfloat16 hi = __float2bfloat16(v);
        sP[rw * PS + c]      = hi;
        sP[rw * PS + 32 + c] = __float2bfloat16(v - __bfloat162float(hi));
    }
    __syncthreads();

    int pp = 0;
    for (int t = 0; t < TOUT; t++) {
        asm volatile("bar.sync %0, %1;" :: "r"(barid), "r"(256) : "memory");
        const __nv_bfloat16* hb = sH + hp * 32 * HS;
        const __nv_bfloat16* pbuf = sP + pp * 32 * PS;
        u32 ah4[4][4], al4[4][4];
        LD_AFRAGS(ah4, al4, hb, HS, R0, R1, tg);
        u32 xh[2][4], xl[2][4];
#pragma unroll
        for (int ks = 0; ks < 2; ks++) {
            const int c0 = ks * 16 + 2 * tg;
            xh[ks][0] = *reinterpret_cast<const u32*>(&pbuf[R0 * PS + c0]);
            xh[ks][1] = *reinterpret_cast<const u32*>(&pbuf[R1 * PS + c0]);
            xh[ks][2] = *reinterpret_cast<const u32*>(&pbuf[R0 * PS + c0 + 8]);
            xh[ks][3] = *reinterpret_cast<const u32*>(&pbuf[R1 * PS + c0 + 8]);
            xl[ks][0] = *reinterpret_cast<const u32*>(&pbuf[R0 * PS + 32 + c0]);
            xl[ks][1] = *reinterpret_cast<const u32*>(&pbuf[R1 * PS + 32 + c0]);
            xl[ks][2] = *reinterpret_cast<const u32*>(&pbuf[R0 * PS + 32 + c0 + 8]);
            xl[ks][3] = *reinterpret_cast<const u32*>(&pbuf[R1 * PS + 32 + c0 + 8]);
        }

        float accW[3][4], accP[4];
#pragma unroll
        for (int nt = 0; nt < 3; nt++) { accW[nt][0]=0.f; accW[nt][1]=0.f; accW[nt][2]=0.f; accW[nt][3]=0.f; }
        accP[0]=0.f; accP[1]=0.f; accP[2]=0.f; accP[3]=0.f;
#pragma unroll
        for (int nt = 0; nt < 3; nt++)
#pragma unroll
            for (int ks = 0; ks < 4; ks++)
                MMA(accW[nt], ah4[ks][0], ah4[ks][1], ah4[ks][2], ah4[ks][3], bh[nt][ks][0], bh[nt][ks][1]);
#pragma unroll
        for (int nt = 0; nt < 3; nt++) {
            float* T = (nt < 2) ? accW[nt] : accP;
#pragma unroll
            for (int ks = 0; ks < 2; ks++) {
                const uint4 w = sWf[((wn * 3 + nt) * 2 + ks) * 32 + lane];
                MMA(T, xh[ks][0], xh[ks][1], xh[ks][2], xh[ks][3], w.x, w.y);
                MMA(T, xl[ks][0], xl[ks][1], xl[ks][2], xl[ks][3], w.x, w.y);
                MMA(T, xh[ks][0], xh[ks][1], xh[ks][2], xh[ks][3], w.z, w.w);
            }
        }
#pragma unroll
        for (int nt = 0; nt < 3; nt++)
#pragma unroll
            for (int ks = 0; ks < 4; ks++)
                MMA(accW[nt], al4[ks][0], al4[ks][1], al4[ks][2], al4[ks][3], bh[nt][ks][0], bh[nt][ks][1]);
#pragma unroll
        for (int nt = 0; nt < 3; nt++)
#pragma unroll
            for (int ks = 0; ks < 4; ks++) {
                const uint2 wl = sWl[((wn * 3 + nt) * 4 + ks) * 32 + lane];
                MMA(accW[nt], ah4[ks][0], ah4[ks][1], ah4[ks][2], ah4[ks][3], wl.x, wl.y);
            }

        __nv_bfloat16* hw = sH + (hp ^ 1) * 32 * HS;
#pragma unroll
        for (int j = 0; j < 4; j++) {
            const int c = j & 1;
            const float rg = fsig(accW[0][j] + br[c]);
            const float zg = fsig(accW[1][j] + bz[c]);
            const float nn = ftanh(accP[j] + ni[c] + rg * (accW[2][j] + nh[c]));
            h[j] = nn + zg * (h[j] - nn);
        }
        {
            const int col = 8 * wn + 2 * tg;
            u32 vh, vl;
            split2(h[0], h[1], vh, vl);
            *reinterpret_cast<u32*>(&hw[R0 * HS + col])      = vh;
            *reinterpret_cast<u32*>(&hw[R0 * HS + 64 + col]) = vl;
            split2(h[2], h[3], vh, vl);
            *reinterpret_cast<u32*>(&hw[R1 * HS + col])      = vh;
            *reinterpret_cast<u32*>(&hw[R1 * HS + 64 + col]) = vl;
        }
        asm volatile("bar.sync %0, %1;" :: "r"(barid), "r"(256) : "memory");

        // projection from NEW h (warps wn<4: col block 8*wn)
        if (wn < 4) {
            const __nv_bfloat16* hn = sH + (hp ^ 1) * 32 * HS;
            __nv_bfloat16* pn = sP + (pp ^ 1) * 32 * PS;
            u32 nh4[4][4], nl4[4][4];
            LD_AFRAGS(nh4, nl4, hn, HS, R0, R1, tg);
            float pacc[4] = {0.f, 0.f, 0.f, 0.f};
#pragma unroll
            for (int ks = 0; ks < 4; ks++) {
                const uint4 w = sPf[(wn * 4 + ks) * 32 + lane];
                MMA(pacc, nh4[ks][0], nh4[ks][1], nh4[ks][2], nh4[ks][3], w.x, w.y);
                MMA(pacc, nl4[ks][0], nl4[ks][1], nl4[ks][2], nl4[ks][3], w.x, w.y);
                MMA(pacc, nh4[ks][0], nh4[ks][1], nh4[ks][2], nh4[ks][3], w.z, w.w);
            }
            const float p00 = pacc[0] + pb0, p01 = pacc[1] + pb1;
            const float p10 = pacc[2] + pb0, p11 = pacc[3] + pb1;
            *reinterpret_cast<float2*>(&out[((size_t)(rowbase + R0) * TOUT + t) * C_ + pcol]) = make_float2(p00, p01);
            *reinterpret_cast<float2*>(&out[((size_t)(rowbase + R1) * TOUT + t) * C_ + pcol]) = make_float2(p10, p11);
            u32 vh, vl;
            split2(p00, p01, vh, vl);
            *reinterpret_cast<u32*>(&pn[R0 * PS + pcol])      = vh;
            *reinterpret_cast<u32*>(&pn[R0 * PS + 32 + pcol]) = vl;
            split2(p10, p11, vh, vl);
            *reinterpret_cast<u32*>(&pn[R1 * PS + pcol])      = vh;
            *reinterpret_cast<u32*>(&pn[R1 * PS + 32 + pcol]) = vl;
        }
        hp ^= 1; pp ^= 1;
    }
}

// ============================ launch ============================
extern "C" void kernel_launch(void* const* d_in, const int* in_sizes, int n_in,
                              void* d_out, int out_size)
{
    (void)in_sizes; (void)n_in; (void)out_size;
    const float* x    = (const float*)d_in[0];
    const float* eWih = (const float*)d_in[1];
    const float* eWhh = (const float*)d_in[2];
    const float* eBih = (const float*)d_in[3];
    const float* eBhh = (const float*)d_in[4];
    const float* dWih = (const float*)d_in[5];
    const float* dWhh = (const float*)d_in[6];
    const float* dBih = (const float*)d_in[7];
    const float* dBhh = (const float*)d_in[8];
    const float* pW   = (const float*)d_in[9];
    const float* pB   = (const float*)d_in[10];
    float* out = (float*)d_out;

    xsplit_kernel<<<(TIN * B_) / 128, 256>>>(x);

    cudaFuncSetAttribute(gru_fused,
                         cudaFuncAttributeMaxDynamicSharedMemorySize, SM_TOTAL);
    gru_fused<<<B_ / 32, 512, SM_TOTAL>>>(
        x, eWih, eWhh, eBih, eBhh, dWih, dWhh, dBih, dBhh, pW, pB, out);
}

// round 12
// speedup vs baseline: 1.1089x; 1.0360x over previous
#include <cuda_runtime.h>
#include <cuda_fp16.h>
#include <cstdint>

// GRU seq2seq forecaster — fused tensor-core recurrence, fp16 weight-split.
//  K0: xsplit — x -> fp16 PERMUTED 64B records (frag-major u32 layout).
//  K1: 256 thr, 8 warps = 2 row-groups x 4 unit-quads. h/x rounded to single
//      fp16 (repr 2^-12); weights split fp16 hi+lo (exact) -> 2 products.
//      72 MMA/warp/step. Frag-major SMEM: h reads = 4 LDS.128, x = 2 LDS.128.

#define B_    4096
#define TIN   168
#define C_    32
#define H_    64
#define TOUT  24

typedef uint32_t u32;
typedef unsigned long long u64;

__device__ u32 g_xs[(size_t)TIN * B_ * 16];   // 44 MB fp16 permuted x records

__device__ __forceinline__ float fsig(float a) {
    return __fdividef(1.0f, 1.0f + __expf(-a));
}
__device__ __forceinline__ float ftanh(float a) {
    float e = __expf(2.0f * a);
    return 1.0f - __fdividef(2.0f, e + 1.0f);
}
// low fp16 = a, high fp16 = b (matches prior bf16 pack convention)
__device__ __forceinline__ u32 packh2(float a, float b) {
    u32 d; asm("cvt.rn.f16x2.f32 %0, %1, %2;" : "=r"(d) : "f"(b), "f"(a)); return d;
}
__device__ __forceinline__ void splith2(float a, float b, u32& hi2, u32& lo2) {
    hi2 = packh2(a, b);
    __half2 hv = *reinterpret_cast<const __half2*>(&hi2);
    lo2 = packh2(a - __low2float(hv), b - __high2float(hv));
}
__device__ __forceinline__ void MMA(float acc[4], u32 a0, u32 a1, u32 a2, u32 a3,
                                    u32 b0, u32 b1) {
    asm volatile(
        "mma.sync.aligned.m16n8k16.row.col.f32.f16.f16.f32 "
        "{%0,%1,%2,%3}, {%4,%5,%6,%7}, {%8,%9}, {%0,%1,%2,%3};"
        : "+f"(acc[0]), "+f"(acc[1]), "+f"(acc[2]), "+f"(acc[3])
        : "r"(a0), "r"(a1), "r"(a2), "r"(a3), "r"(b0), "r"(b1));
}
__device__ __forceinline__ u32 smem_u32(const void* p) {
    u32 a;
    asm("{ .reg .u64 t; cvta.to.shared.u64 t, %1; cvt.u32.u64 %0, t; }" : "=r"(a) : "l"(p));
    return a;
}
__device__ __forceinline__ void cp16(u32 daddr, const void* gsrc) {
    asm volatile("cp.async.cg.shared.global [%0], [%1], 16;"
                 :: "r"(daddr), "l"(gsrc) : "memory");
}

// ============================ kernel 0: x pre-split (fp16, permuted) ============================
// record[j] = packh2(x[2w], x[2w+1]) at position j where w = (j%4)*4 + j/4.
__global__ __launch_bounds__(256)
void xsplit_kernel(const float* __restrict__ x)
{
    const int p = blockIdx.x * 256 + threadIdx.x;      // t*B + b
    const int t = p >> 12, b = p & (B_ - 1);
    const float* src = x + ((size_t)b * TIN + t) * C_;
    u32 s[16];
#pragma unroll
    for (int w = 0; w < 16; w++) s[w] = packh2(src[2 * w], src[2 * w + 1]);
    uint4* dst = reinterpret_cast<uint4*>(g_xs + (size_t)p * 16);
#pragma unroll
    for (int j4 = 0; j4 < 4; j4++)
        dst[j4] = make_uint4(s[j4], s[4 + j4], s[8 + j4], s[12 + j4]);
}

// ============================ kernel 1: fused recurrence ============================
#define HSu 36     // sH row stride (u32): 32 data + 4 pad (conflict-free LDS.128)
#define PSu 16     // prev row stride (u32): 64B exact
#define XSu 16     // x row stride (u32): 64B exact

#define OFF_H   0                         // [2 par][32][HSu] u32 = 9216
#define OFF_P   9216                      // [2 par][32][PSu] u32 = 4096
#define OFF_X   13312                     // [2 grp][2 buf][16][XSu] u32 = 4096
#define OFF_WF  17408                     // [4 wq][6 nt][2 ks][32] uint4 = 24576
#define OFF_PF  41984                     // [4 wq][4 ks][32] uint4 = 8192
#define SM_TOTAL 50176

__device__ __forceinline__ int permrow(int ln, int wq) {
    return (ln >> 4) * 64 + 16 * wq + (ln & 15);
}

// Extract A-frags from two row-vectors (uint4 pairs): a-index mapping verified R7-R10.
#define AFRAG_FROM(v0a, v0b, v1a, v1b, a0, a1, a2, a3)                     \
    a0[0]=(v0a).x; a2[0]=(v0a).y; a1[0]=(v1a).x; a3[0]=(v1a).y;            \
    a0[1]=(v0a).z; a2[1]=(v0a).w; a1[1]=(v1a).z; a3[1]=(v1a).w;            \
    a0[2]=(v0b).x; a2[2]=(v0b).y; a1[2]=(v1b).x; a3[2]=(v1b).y;            \
    a0[3]=(v0b).z; a2[3]=(v0b).w; a1[3]=(v1b).z; a3[3]=(v1b).w;

__global__ __launch_bounds__(256)
void gru_fused(const float* __restrict__ x,
               const float* __restrict__ eWih, const float* __restrict__ eWhh,
               const float* __restrict__ eBih, const float* __restrict__ eBhh,
               const float* __restrict__ dWih, const float* __restrict__ dWhh,
               const float* __restrict__ dBih, const float* __restrict__ dBhh,
               const float* __restrict__ pW,   const float* __restrict__ pB,
               float* __restrict__ out)
{
    extern __shared__ __align__(16) char smem[];
    u32* sHu   = reinterpret_cast<u32*>(smem + OFF_H);
    u32* sPu   = reinterpret_cast<u32*>(smem + OFF_P);
    const u32* sXu = reinterpret_cast<const u32*>(smem + OFF_X);
    uint4* sWf = reinterpret_cast<uint4*>(smem + OFF_WF);
    uint4* sPf = reinterpret_cast<uint4*>(smem + OFF_PF);
    const u32 smb = smem_u32(smem);

    const int tid  = threadIdx.x;
    const int wid  = tid >> 5;
    const int lane = tid & 31;
    const int g  = lane >> 2;
    const int tg = lane & 3;
    const int mh = wid >> 2;           // row-group (0,1): rows mh*16..+15
    const int wq = wid & 3;            // unit quad: units 16wq..16wq+15
    const int R0 = mh * 16 + g, R1 = R0 + 8;
    const int lr0 = g, lr1 = g + 8;    // group-local x rows
    const int rowbase = blockIdx.x * 32;
    const int barid = 1 + mh;
    const int lt = tid & 127;

    // ---- zero h buffers ----
    for (int i = tid; i < 2 * 32 * HSu; i += 256) sHu[i] = 0;

    // ---- stage encoder Wih frags (group 0), fp16 split hi/lo ----
    if (mh == 0) {
#pragma unroll
        for (int nt = 0; nt < 6; nt++)
#pragma unroll
            for (int ks = 0; ks < 2; ks++) {
                const float* wr = eWih + permrow(nt * 8 + g, wq) * 32 + ks * 16 + 2 * tg;
                u32 h0, l0, h1, l1;
                splith2(wr[0], wr[1], h0, l0);
                splith2(wr[8], wr[9], h1, l1);
                sWf[((wq * 6 + nt) * 2 + ks) * 32 + lane] = make_uint4(h0, h1, l0, l1);
            }
    }
    // ---- encoder Whh frags: hi + lo fp16 in registers (96 u32) ----
    u32 bh[6][4][2], bw[6][4][2];
#pragma unroll
    for (int nt = 0; nt < 6; nt++) {
        const float* row = eWhh + permrow(nt * 8 + g, wq) * 64;
#pragma unroll
        for (int ks = 0; ks < 4; ks++) {
            const int k0 = ks * 16 + 2 * tg;
            splith2(row[k0],     row[k0 + 1], bh[nt][ks][0], bw[nt][ks][0]);
            splith2(row[k0 + 8], row[k0 + 9], bh[nt][ks][1], bw[nt][ks][1]);
        }
    }
    float ebr[4], ebz[4], eni[4], enh[4];
#pragma unroll
    for (int sp = 0; sp < 4; sp++) {
        const int u = 16 * wq + (sp >> 1) * 8 + 2 * tg + (sp & 1);
        ebr[sp] = eBih[u] + eBhh[u];
        ebz[sp] = eBih[64 + u] + eBhh[64 + u];
        eni[sp] = eBih[128 + u];
        enh[sp] = eBhh[128 + u];
    }
    __syncthreads();

    // prologue: prefetch own group's x tile t=0 (16 rows x 64B)
    if (lt < 64) {
        const int row = lt >> 2, ch = lt & 3;
        const char* src = reinterpret_cast<const char*>(
            g_xs + ((size_t)(rowbase + mh * 16 + row)) * 16) + ch * 16;
        cp16(smb + OFF_X + mh * 2048 + row * 64 + ch * 16, src);
        asm volatile("cp.async.commit_group;" ::: "memory");
    }

    float h[8];
#pragma unroll
    for (int e = 0; e < 8; e++) h[e] = 0.0f;
    int hp = 0;

    // ======================= encoder: 168 steps =======================
    for (int t = 0; t < TIN; t++) {
        asm volatile("cp.async.wait_group 0;" ::: "memory");
        asm volatile("bar.sync %0, %1;" :: "r"(barid), "r"(128) : "memory");
        if (t + 1 < TIN && lt < 64) {
            const int row = lt >> 2, ch = lt & 3;
            const char* src = reinterpret_cast<const char*>(
                g_xs + ((size_t)(t + 1) * B_ + rowbase + mh * 16 + row) * 16) + ch * 16;
            cp16(smb + OFF_X + mh * 2048 + ((t + 1) & 1) * 1024 + row * 64 + ch * 16, src);
            asm volatile("cp.async.commit_group;" ::: "memory");
        }

        // h A-frags (fp16, frag-major): 4 LDS.128
        const u32* hbu = sHu + hp * (32 * HSu);
        const uint4* h0p = reinterpret_cast<const uint4*>(hbu + R0 * HSu + tg * 8);
        const uint4* h1p = reinterpret_cast<const uint4*>(hbu + R1 * HSu + tg * 8);
        const uint4 v0a = h0p[0], v0b = h0p[1], v1a = h1p[0], v1b = h1p[1];
        u32 a0[4], a1[4], a2[4], a3[4];
        AFRAG_FROM(v0a, v0b, v1a, v1b, a0, a1, a2, a3);

        // x A-frags: 2 LDS.128
        const u32* xb = sXu + mh * 512 + (t & 1) * 256;
        const uint4 xv0 = *reinterpret_cast<const uint4*>(xb + lr0 * XSu + tg * 4);
        const uint4 xv1 = *reinterpret_cast<const uint4*>(xb + lr1 * XSu + tg * 4);
        u32 x0[2], x1[2], x2[2], x3[2];
        x0[0]=xv0.x; x2[0]=xv0.y; x0[1]=xv0.z; x2[1]=xv0.w;
        x1[0]=xv1.x; x3[0]=xv1.y; x1[1]=xv1.z; x3[1]=xv1.w;

        float accW[6][4], accP[2][4];
#pragma unroll
        for (int q = 0; q < 2; q++) { accP[q][0]=0.f; accP[q][1]=0.f; accP[q][2]=0.f; accP[q][3]=0.f; }
#pragma unroll
        for (int nt = 0; nt < 6; nt++) {
            float* A = accW[nt];
            A[0]=0.f; A[1]=0.f; A[2]=0.f; A[3]=0.f;
#pragma unroll
            for (int ks = 0; ks < 4; ks++)
                MMA(A, a0[ks], a1[ks], a2[ks], a3[ks], bh[nt][ks][0], bh[nt][ks][1]);
#pragma unroll
            for (int ks = 0; ks < 4; ks++)
                MMA(A, a0[ks], a1[ks], a2[ks], a3[ks], bw[nt][ks][0], bw[nt][ks][1]);
            float* T = (nt < 4) ? A : accP[nt - 4];
#pragma unroll
            for (int ks = 0; ks < 2; ks++) {
                const uint4 w = sWf[((wq * 6 + nt) * 2 + ks) * 32 + lane];
                MMA(T, x0[ks], x1[ks], x2[ks], x3[ks], w.x, w.y);
                MMA(T, x0[ks], x1[ks], x2[ks], x3[ks], w.z, w.w);
            }
        }

        // gates + h update + fp16 store (frag-major positions)
        u32* hwu = sHu + (hp ^ 1) * (32 * HSu);
#pragma unroll
        for (int rh = 0; rh < 2; rh++) {
#pragma unroll
            for (int s = 0; s < 2; s++) {
                const int e = rh * 4 + s * 2;
                const float rg0 = fsig(accW[s][2*rh]   + ebr[s*2]);
                const float rg1 = fsig(accW[s][2*rh+1] + ebr[s*2+1]);
                const float z0  = fsig(accW[2+s][2*rh]   + ebz[s*2]);
                const float z1  = fsig(accW[2+s][2*rh+1] + ebz[s*2+1]);
                const float n0  = ftanh(accP[s][2*rh]   + eni[s*2]   + rg0 * (accW[4+s][2*rh]   + enh[s*2]));
                const float n1  = ftanh(accP[s][2*rh+1] + eni[s*2+1] + rg1 * (accW[4+s][2*rh+1] + enh[s*2+1]));
                h[e]   = n0 + z0 * (h[e]   - n0);
                h[e+1] = n1 + z1 * (h[e+1] - n1);
            }
        }
#pragma unroll
        for (int rh = 0; rh < 2; rh++) {
            const u32 p0 = packh2(h[rh*4+0], h[rh*4+1]);   // s=0 cols
            const u32 p1 = packh2(h[rh*4+2], h[rh*4+3]);   // s=1 cols
            const int row = rh ? R1 : R0;
            *reinterpret_cast<u64*>(&hwu[row * HSu + tg * 8 + 2 * wq]) =
                ((u64)p1 << 32) | p0;
        }
        hp ^= 1;
    }

    // ======================= decoder: 24 steps =======================
    __syncthreads();
    if (mh == 0) {   // restage: decoder Wih frags + projection W frags
#pragma unroll
        for (int nt = 0; nt < 6; nt++)
#pragma unroll
            for (int ks = 0; ks < 2; ks++) {
                const float* wr = dWih + permrow(nt * 8 + g, wq) * 32 + ks * 16 + 2 * tg;
                u32 h0, l0, h1, l1;
                splith2(wr[0], wr[1], h0, l0);
                splith2(wr[8], wr[9], h1, l1);
                sWf[((wq * 6 + nt) * 2 + ks) * 32 + lane] = make_uint4(h0, h1, l0, l1);
            }
#pragma unroll
        for (int ks = 0; ks < 4; ks++) {
            const float* wr = pW + (8 * wq + g) * 64 + ks * 16 + 2 * tg;
            u32 h0, l0, h1, l1;
            splith2(wr[0], wr[1], h0, l0);
            splith2(wr[8], wr[9], h1, l1);
            sPf[(wq * 4 + ks) * 32 + lane] = make_uint4(h0, h1, l0, l1);
        }
    }
    // decoder Whh frags
#pragma unroll
    for (int nt = 0; nt < 6; nt++) {
        const float* row = dWhh + permrow(nt * 8 + g, wq) * 64;
#pragma unroll
        for (int ks = 0; ks < 4; ks++) {
            const int k0 = ks * 16 + 2 * tg;
            splith2(row[k0],     row[k0 + 1], bh[nt][ks][0], bw[nt][ks][0]);
            splith2(row[k0 + 8], row[k0 + 9], bh[nt][ks][1], bw[nt][ks][1]);
        }
    }
    float dbr[4], dbz[4], dni[4], dnh[4];
#pragma unroll
    for (int sp = 0; sp < 4; sp++) {
        const int u = 16 * wq + (sp >> 1) * 8 + 2 * tg + (sp & 1);
        dbr[sp] = dBih[u] + dBhh[u];
        dbz[sp] = dBih[64 + u] + dBhh[64 + u];
        dni[sp] = dBih[128 + u];
        dnh[sp] = dBhh[128 + u];
    }
    const int pcol = 8 * wq + 2 * tg;
    const float pb0 = pB[pcol], pb1 = pB[pcol + 1];

    // prev_0 = x[:, TIN-1, :] — copy pre-split permuted records from g_xs
    for (int i = lt; i < 16 * 16; i += 128) {
        const int row = i >> 4, w = i & 15;
        sPu[(mh * 16 + row) * PSu + w] =
            g_xs[((size_t)(TIN - 1) * B_ + rowbase + mh * 16 + row) * 16 + w];
    }
    __syncthreads();

    int pp = 0;
    for (int t = 0; t < TOUT; t++) {
        const u32* hbu = sHu + hp * (32 * HSu);
        const uint4* h0p = reinterpret_cast<const uint4*>(hbu + R0 * HSu + tg * 8);
        const uint4* h1p = reinterpret_cast<const uint4*>(hbu + R1 * HSu + tg * 8);
        const uint4 v0a = h0p[0], v0b = h0p[1], v1a = h1p[0], v1b = h1p[1];
        u32 a0[4], a1[4], a2[4], a3[4];
        AFRAG_FROM(v0a, v0b, v1a, v1b, a0, a1, a2, a3);

        const u32* pbu = sPu + pp * (32 * PSu);
        const uint4 pv0 = *reinterpret_cast<const uint4*>(pbu + R0 * PSu + tg * 4);
        const uint4 pv1 = *reinterpret_cast<const uint4*>(pbu + R1 * PSu + tg * 4);
        u32 x0[2], x1[2], x2[2], x3[2];
        x0[0]=pv0.x; x2[0]=pv0.y; x0[1]=pv0.z; x2[1]=pv0.w;
        x1[0]=pv1.x; x3[0]=pv1.y; x1[1]=pv1.z; x3[1]=pv1.w;

        float accW[6][4], accP[2][4];
#pragma unroll
        for (int q = 0; q < 2; q++) { accP[q][0]=0.f; accP[q][1]=0.f; accP[q][2]=0.f; accP[q][3]=0.f; }
#pragma unroll
        for (int nt = 0; nt < 6; nt++) {
            float* A = accW[nt];
            A[0]=0.f; A[1]=0.f; A[2]=0.f; A[3]=0.f;
#pragma unroll
            for (int ks = 0; ks < 4; ks++)
                MMA(A, a0[ks], a1[ks], a2[ks], a3[ks], bh[nt][ks][0], bh[nt][ks][1]);
#pragma unroll
            for (int ks = 0; ks < 4; ks++)
                MMA(A, a0[ks], a1[ks], a2[ks], a3[ks], bw[nt][ks][0], bw[nt][ks][1]);
            float* T = (nt < 4) ? A : accP[nt - 4];
#pragma unroll
            for (int ks = 0; ks < 2; ks++) {
                const uint4 w = sWf[((wq * 6 + nt) * 2 + ks) * 32 + lane];
                MMA(T, x0[ks], x1[ks], x2[ks], x3[ks], w.x, w.y);
                MMA(T, x0[ks], x1[ks], x2[ks], x3[ks], w.z, w.w);
            }
        }

        u32* hwu = sHu + (hp ^ 1) * (32 * HSu);
#pragma unroll
        for (int rh = 0; rh < 2; rh++) {
#pragma unroll
            for (int s = 0; s < 2; s++) {
                const int e = rh * 4 + s * 2;
                const float rg0 = fsig(accW[s][2*rh]   + dbr[s*2]);
                const float rg1 = fsig(accW[s][2*rh+1] + dbr[s*2+1]);
                const float z0  = fsig(accW[2+s][2*rh]   + dbz[s*2]);
                const float z1  = fsig(accW[2+s][2*rh+1] + dbz[s*2+1]);
                const float n0  = ftanh(accP[s][2*rh]   + dni[s*2]   + rg0 * (accW[4+s][2*rh]   + dnh[s*2]));
                const float n1  = ftanh(accP[s][2*rh+1] + dni[s*2+1] + rg1 * (accW[4+s][2*rh+1] + dnh[s*2+1]));
                h[e]   = n0 + z0 * (h[e]   - n0);
                h[e+1] = n1 + z1 * (h[e+1] - n1);
            }
        }
#pragma unroll
        for (int rh = 0; rh < 2; rh++) {
            const u32 p0 = packh2(h[rh*4+0], h[rh*4+1]);
            const u32 p1 = packh2(h[rh*4+2], h[rh*4+3]);
            const int row = rh ? R1 : R0;
            *reinterpret_cast<u64*>(&hwu[row * HSu + tg * 8 + 2 * wq]) =
                ((u64)p1 << 32) | p0;
        }
        asm volatile("bar.sync %0, %1;" :: "r"(barid), "r"(128) : "memory");

        // projection from NEW h (warp wq -> output cols 8wq..8wq+7)
        {
            const u32* hnu = sHu + (hp ^ 1) * (32 * HSu);
            const uint4* n0p = reinterpret_cast<const uint4*>(hnu + R0 * HSu + tg * 8);
            const uint4* n1p = reinterpret_cast<const uint4*>(hnu + R1 * HSu + tg * 8);
            const uint4 w0a = n0p[0], w0b = n0p[1], w1a = n1p[0], w1b = n1p[1];
            u32 n0[4], n1[4], n2[4], n3[4];
            AFRAG_FROM(w0a, w0b, w1a, w1b, n0, n1, n2, n3);
            float pacc[4] = {0.f, 0.f, 0.f, 0.f};
#pragma unroll
            for (int ks = 0; ks < 4; ks++) {
                const uint4 w = sPf[(wq * 4 + ks) * 32 + lane];
                MMA(pacc, n0[ks], n1[ks], n2[ks], n3[ks], w.x, w.y);
                MMA(pacc, n0[ks], n1[ks], n2[ks], n3[ks], w.z, w.w);
            }
            const float p00 = pacc[0] + pb0, p01 = pacc[1] + pb1;
            const float p10 = pacc[2] + pb0, p11 = pacc[3] + pb1;
            *reinterpret_cast<float2*>(&out[((size_t)(rowbase + R0) * TOUT + t) * C_ + pcol]) = make_float2(p00, p01);
            *reinterpret_cast<float2*>(&out[((size_t)(rowbase + R1) * TOUT + t) * C_ + pcol]) = make_float2(p10, p11);
            // next prev (fp16 permuted): u32 col w = 4wq+tg -> position tg*4+wq
            u32* pnu = sPu + (pp ^ 1) * (32 * PSu);
            pnu[R0 * PSu + tg * 4 + wq] = packh2(p00, p01);
            pnu[R1 * PSu + tg * 4 + wq] = packh2(p10, p11);
        }
        asm volatile("bar.sync %0, %1;" :: "r"(barid), "r"(128) : "memory");
        hp ^= 1; pp ^= 1;
    }
}

// ============================ launch ============================
extern "C" void kernel_launch(void* const* d_in, const int* in_sizes, int n_in,
                              void* d_out, int out_size)
{
    (void)in_sizes; (void)n_in; (void)out_size;
    const float* x    = (const float*)d_in[0];
    const float* eWih = (const float*)d_in[1];
    const float* eWhh = (const float*)d_in[2];
    const float* eBih = (const float*)d_in[3];
    const float* eBhh = (const float*)d_in[4];
    const float* dWih = (const float*)d_in[5];
    const float* dWhh = (const float*)d_in[6];
    const float* dBih = (const float*)d_in[7];
    const float* dBhh = (const float*)d_in[8];
    const float* pW   = (const float*)d_in[9];
    const float* pB   = (const float*)d_in[10];
    float* out = (float*)d_out;

    xsplit_kernel<<<(TIN * B_) / 256, 256>>>(x);

    cudaFuncSetAttribute(gru_fused,
                         cudaFuncAttributeMaxDynamicSharedMemorySize, SM_TOTAL);
    gru_fused<<<B_ / 32, 256, SM_TOTAL>>>(
        x, eWih, eWhh, eBih, eBhh, dWih, dWhh, dBih, dBhh, pW, pB, out);
}

// round 13
// speedup vs baseline: 1.7955x; 1.6192x over previous
#include <cuda_runtime.h>
#include <cuda_fp16.h>
#include <cstdint>

// GRU seq2seq forecaster — fused tensor-core recurrence (fp16 split, tanh.approx).
//  K0: xsplit — x -> fp16 PERMUTED 64B records (frag-major u32 layout), LDG.128.
//  K1: 256 thr, 8 warps = 2 row-groups x 4 unit-quads. h/x single fp16; Whh split
//      fp16 hi+lo (2 products); Wih hi only (x already rounded). 60 MMA/warp/step.
//      Activations via MUFU.TANH. Biases pre-folded into accumulator init.

#define B_    4096
#define TIN   168
#define C_    32
#define H_    64
#define TOUT  24

typedef uint32_t u32;
typedef unsigned long long u64;

__device__ u32 g_xs[(size_t)TIN * B_ * 16];   // 44 MB fp16 permuted x records

__device__ __forceinline__ float tanhap(float a) {
    float r; asm("tanh.approx.f32 %0, %1;" : "=f"(r) : "f"(a)); return r;
}
__device__ __forceinline__ float fsig(float a) {           // sigma(a) = 0.5 + 0.5*tanh(a/2)
    return fmaf(tanhap(0.5f * a), 0.5f, 0.5f);
}
// low fp16 = a, high fp16 = b
__device__ __forceinline__ u32 packh2(float a, float b) {
    u32 d; asm("cvt.rn.f16x2.f32 %0, %1, %2;" : "=r"(d) : "f"(b), "f"(a)); return d;
}
__device__ __forceinline__ void splith2(float a, float b, u32& hi2, u32& lo2) {
    hi2 = packh2(a, b);
    __half2 hv = *reinterpret_cast<const __half2*>(&hi2);
    lo2 = packh2(a - __low2float(hv), b - __high2float(hv));
}
__device__ __forceinline__ void MMA(float acc[4], u32 a0, u32 a1, u32 a2, u32 a3,
                                    u32 b0, u32 b1) {
    asm volatile(
        "mma.sync.aligned.m16n8k16.row.col.f32.f16.f16.f32 "
        "{%0,%1,%2,%3}, {%4,%5,%6,%7}, {%8,%9}, {%0,%1,%2,%3};"
        : "+f"(acc[0]), "+f"(acc[1]), "+f"(acc[2]), "+f"(acc[3])
        : "r"(a0), "r"(a1), "r"(a2), "r"(a3), "r"(b0), "r"(b1));
}
__device__ __forceinline__ u32 smem_u32(const void* p) {
    u32 a;
    asm("{ .reg .u64 t; cvta.to.shared.u64 t, %1; cvt.u32.u64 %0, t; }" : "=r"(a) : "l"(p));
    return a;
}
__device__ __forceinline__ void cp16(u32 daddr, const void* gsrc) {
    asm volatile("cp.async.cg.shared.global [%0], [%1], 16;"
                 :: "r"(daddr), "l"(gsrc) : "memory");
}

// ============================ kernel 0: x pre-split (fp16, permuted) ============================
// record[j] = packh2(x[2w], x[2w+1]) at position j where w = (j%4)*4 + j/4.
__global__ __launch_bounds__(256)
void xsplit_kernel(const float* __restrict__ x)
{
    const int p = blockIdx.x * 256 + threadIdx.x;      // t*B + b
    const int t = p >> 12, b = p & (B_ - 1);
    const float4* s4 = reinterpret_cast<const float4*>(x + ((size_t)b * TIN + t) * C_);
    float4 v[8];
#pragma unroll
    for (int i = 0; i < 8; i++) v[i] = s4[i];          // 8x LDG.128
    u32 s[16];
#pragma unroll
    for (int i = 0; i < 8; i++) {
        s[2 * i]     = packh2(v[i].x, v[i].y);
        s[2 * i + 1] = packh2(v[i].z, v[i].w);
    }
    uint4* dst = reinterpret_cast<uint4*>(g_xs + (size_t)p * 16);
#pragma unroll
    for (int j4 = 0; j4 < 4; j4++)
        dst[j4] = make_uint4(s[j4], s[4 + j4], s[8 + j4], s[12 + j4]);
}

// ============================ kernel 1: fused recurrence ============================
#define HSu 36     // sH row stride (u32): 32 data + 4 pad
#define PSu 16     // prev row stride (u32)
#define XSu 16     // x row stride (u32)

#define OFF_H   0                         // [2 par][32][HSu] u32 = 9216
#define OFF_P   9216                      // [2 par][32][PSu] u32 = 4096
#define OFF_X   13312                     // [2 grp][2 buf][16][XSu] u32 = 4096
#define OFF_WF  17408                     // [4 wq][6 nt][2 ks][32] uint2 = 12288
#define OFF_PF  29696                     // [4 wq][4 ks][32] uint4 = 8192
#define SM_TOTAL 37888

__device__ __forceinline__ int permrow(int ln, int wq) {
    return (ln >> 4) * 64 + 16 * wq + (ln & 15);
}
#define AFRAG_FROM(v0a, v0b, v1a, v1b, a0, a1, a2, a3)                     \
    a0[0]=(v0a).x; a2[0]=(v0a).y; a1[0]=(v1a).x; a3[0]=(v1a).y;            \
    a0[1]=(v0a).z; a2[1]=(v0a).w; a1[1]=(v1a).z; a3[1]=(v1a).w;            \
    a0[2]=(v0b).x; a2[2]=(v0b).y; a1[2]=(v1b).x; a3[2]=(v1b).y;            \
    a0[3]=(v0b).z; a2[3]=(v0b).w; a1[3]=(v1b).z; a3[3]=(v1b).w;

__global__ __launch_bounds__(256)
void gru_fused(const float* __restrict__ x,
               const float* __restrict__ eWih, const float* __restrict__ eWhh,
               const float* __restrict__ eBih, const float* __restrict__ eBhh,
               const float* __restrict__ dWih, const float* __restrict__ dWhh,
               const float* __restrict__ dBih, const float* __restrict__ dBhh,
               const float* __restrict__ pW,   const float* __restrict__ pB,
               float* __restrict__ out)
{
    extern __shared__ __align__(16) char smem[];
    u32* sHu       = reinterpret_cast<u32*>(smem + OFF_H);
    u32* sPu       = reinterpret_cast<u32*>(smem + OFF_P);
    const u32* sXu = reinterpret_cast<const u32*>(smem + OFF_X);
    uint2* sWf     = reinterpret_cast<uint2*>(smem + OFF_WF);
    uint4* sPf     = reinterpret_cast<uint4*>(smem + OFF_PF);
    const u32 smb = smem_u32(smem);

    const int tid  = threadIdx.x;
    const int wid  = tid >> 5;
    const int lane = tid & 31;
    const int g  = lane >> 2;
    const int tg = lane & 3;
    const int mh = wid >> 2;           // row-group (0,1)
    const int wq = wid & 3;            // unit quad
    const int R0 = mh * 16 + g, R1 = R0 + 8;
    const int lr0 = g, lr1 = g + 8;
    const int rowbase = blockIdx.x * 32;
    const int barid = 1 + mh;
    const int lt = tid & 127;

    for (int i = tid; i < 2 * 32 * HSu; i += 256) sHu[i] = 0;

    // ---- stage encoder Wih frags (hi fp16 only) ----
    if (mh == 0) {
#pragma unroll
        for (int nt = 0; nt < 6; nt++)
#pragma unroll
            for (int ks = 0; ks < 2; ks++) {
                const float* wr = eWih + permrow(nt * 8 + g, wq) * 32 + ks * 16 + 2 * tg;
                sWf[((wq * 6 + nt) * 2 + ks) * 32 + lane] =
                    make_uint2(packh2(wr[0], wr[1]), packh2(wr[8], wr[9]));
            }
    }
    // ---- encoder Whh frags: hi + lo fp16 in registers ----
    u32 bh[6][4][2], bw[6][4][2];
#pragma unroll
    for (int nt = 0; nt < 6; nt++) {
        const float* row = eWhh + permrow(nt * 8 + g, wq) * 64;
#pragma unroll
        for (int ks = 0; ks < 4; ks++) {
            const int k0 = ks * 16 + 2 * tg;
            splith2(row[k0],     row[k0 + 1], bh[nt][ks][0], bw[nt][ks][0]);
            splith2(row[k0 + 8], row[k0 + 9], bh[nt][ks][1], bw[nt][ks][1]);
        }
    }
    float ebr[4], ebz[4], eni[4], enh[4];
#pragma unroll
    for (int sp = 0; sp < 4; sp++) {
        const int u = 16 * wq + (sp >> 1) * 8 + 2 * tg + (sp & 1);
        ebr[sp] = eBih[u] + eBhh[u];
        ebz[sp] = eBih[64 + u] + eBhh[64 + u];
        eni[sp] = eBih[128 + u];
        enh[sp] = eBhh[128 + u];
    }
    __syncthreads();

    if (lt < 64) {
        const int row = lt >> 2, ch = lt & 3;
        const char* src = reinterpret_cast<const char*>(
            g_xs + ((size_t)(rowbase + mh * 16 + row)) * 16) + ch * 16;
        cp16(smb + OFF_X + mh * 2048 + row * 64 + ch * 16, src);
        asm volatile("cp.async.commit_group;" ::: "memory");
    }

    float h[8];
#pragma unroll
    for (int e = 0; e < 8; e++) h[e] = 0.0f;
    int hp = 0;

    // ======================= encoder: 168 steps =======================
    for (int t = 0; t < TIN; t++) {
        asm volatile("cp.async.wait_group 0;" ::: "memory");
        asm volatile("bar.sync %0, %1;" :: "r"(barid), "r"(128) : "memory");
        if (t + 1 < TIN && lt < 64) {
            const int row = lt >> 2, ch = lt & 3;
            const char* src = reinterpret_cast<const char*>(
                g_xs + ((size_t)(t + 1) * B_ + rowbase + mh * 16 + row) * 16) + ch * 16;
            cp16(smb + OFF_X + mh * 2048 + ((t + 1) & 1) * 1024 + row * 64 + ch * 16, src);
            asm volatile("cp.async.commit_group;" ::: "memory");
        }

        const u32* hbu = sHu + hp * (32 * HSu);
        const uint4* h0p = reinterpret_cast<const uint4*>(hbu + R0 * HSu + tg * 8);
        const uint4* h1p = reinterpret_cast<const uint4*>(hbu + R1 * HSu + tg * 8);
        const uint4 v0a = h0p[0], v0b = h0p[1], v1a = h1p[0], v1b = h1p[1];
        u32 a0[4], a1[4], a2[4], a3[4];
        AFRAG_FROM(v0a, v0b, v1a, v1b, a0, a1, a2, a3);

        const u32* xb = sXu + mh * 512 + (t & 1) * 256;
        const uint4 xv0 = *reinterpret_cast<const uint4*>(xb + lr0 * XSu + tg * 4);
        const uint4 xv1 = *reinterpret_cast<const uint4*>(xb + lr1 * XSu + tg * 4);
        u32 x0[2], x1[2], x2[2], x3[2];
        x0[0]=xv0.x; x2[0]=xv0.y; x0[1]=xv0.z; x2[1]=xv0.w;
        x1[0]=xv1.x; x3[0]=xv1.y; x1[1]=xv1.z; x3[1]=xv1.w;

        // accumulators pre-loaded with biases
        float accW[6][4], accP[2][4];
#pragma unroll
        for (int s = 0; s < 2; s++)
#pragma unroll
            for (int j = 0; j < 4; j++) {
                const int c = s * 2 + (j & 1);
                accW[s][j]     = ebr[c];
                accW[2 + s][j] = ebz[c];
                accW[4 + s][j] = enh[c];
                accP[s][j]     = eni[c];
            }
#pragma unroll
        for (int nt = 0; nt < 6; nt++) {
            float* A = accW[nt];
#pragma unroll
            for (int ks = 0; ks < 4; ks++)
                MMA(A, a0[ks], a1[ks], a2[ks], a3[ks], bh[nt][ks][0], bh[nt][ks][1]);
#pragma unroll
            for (int ks = 0; ks < 4; ks++)
                MMA(A, a0[ks], a1[ks], a2[ks], a3[ks], bw[nt][ks][0], bw[nt][ks][1]);
            float* T = (nt < 4) ? A : accP[nt - 4];
#pragma unroll
            for (int ks = 0; ks < 2; ks++) {
                const uint2 w = sWf[((wq * 6 + nt) * 2 + ks) * 32 + lane];
                MMA(T, x0[ks], x1[ks], x2[ks], x3[ks], w.x, w.y);
            }
        }

        u32* hwu = sHu + (hp ^ 1) * (32 * HSu);
#pragma unroll
        for (int rh = 0; rh < 2; rh++) {
#pragma unroll
            for (int s = 0; s < 2; s++) {
                const int e = rh * 4 + s * 2;
                const float rg0 = fsig(accW[s][2*rh]);
                const float rg1 = fsig(accW[s][2*rh+1]);
                const float z0  = fsig(accW[2+s][2*rh]);
                const float z1  = fsig(accW[2+s][2*rh+1]);
                const float n0  = tanhap(fmaf(rg0, accW[4+s][2*rh],   accP[s][2*rh]));
                const float n1  = tanhap(fmaf(rg1, accW[4+s][2*rh+1], accP[s][2*rh+1]));
                h[e]   = n0 + z0 * (h[e]   - n0);
                h[e+1] = n1 + z1 * (h[e+1] - n1);
            }
        }
#pragma unroll
        for (int rh = 0; rh < 2; rh++) {
            const u32 p0 = packh2(h[rh*4+0], h[rh*4+1]);
            const u32 p1 = packh2(h[rh*4+2], h[rh*4+3]);
            const int row = rh ? R1 : R0;
            *reinterpret_cast<u64*>(&hwu[row * HSu + tg * 8 + 2 * wq]) =
                ((u64)p1 << 32) | p0;
        }
        hp ^= 1;
    }

    // ======================= decoder: 24 steps =======================
    __syncthreads();
    if (mh == 0) {
#pragma unroll
        for (int nt = 0; nt < 6; nt++)
#pragma unroll
            for (int ks = 0; ks < 2; ks++) {
                const float* wr = dWih + permrow(nt * 8 + g, wq) * 32 + ks * 16 + 2 * tg;
                sWf[((wq * 6 + nt) * 2 + ks) * 32 + lane] =
                    make_uint2(packh2(wr[0], wr[1]), packh2(wr[8], wr[9]));
            }
#pragma unroll
        for (int ks = 0; ks < 4; ks++) {
            const float* wr = pW + (8 * wq + g) * 64 + ks * 16 + 2 * tg;
            u32 h0, l0, h1, l1;
            splith2(wr[0], wr[1], h0, l0);
            splith2(wr[8], wr[9], h1, l1);
            sPf[(wq * 4 + ks) * 32 + lane] = make_uint4(h0, h1, l0, l1);
        }
    }
#pragma unroll
    for (int nt = 0; nt < 6; nt++) {
        const float* row = dWhh + permrow(nt * 8 + g, wq) * 64;
#pragma unroll
        for (int ks = 0; ks < 4; ks++) {
            const int k0 = ks * 16 + 2 * tg;
            splith2(row[k0],     row[k0 + 1], bh[nt][ks][0], bw[nt][ks][0]);
            splith2(row[k0 + 8], row[k0 + 9], bh[nt][ks][1], bw[nt][ks][1]);
        }
    }
    float dbr[4], dbz[4], dni[4], dnh[4];
#pragma unroll
    for (int sp = 0; sp < 4; sp++) {
        const int u = 16 * wq + (sp >> 1) * 8 + 2 * tg + (sp & 1);
        dbr[sp] = dBih[u] + dBhh[u];
        dbz[sp] = dBih[64 + u] + dBhh[64 + u];
        dni[sp] = dBih[128 + u];
        dnh[sp] = dBhh[128 + u];
    }
    const int pcol = 8 * wq + 2 * tg;
    const float pb0 = pB[pcol], pb1 = pB[pcol + 1];

    for (int i = lt; i < 16 * 16; i += 128) {
        const int row = i >> 4, w = i & 15;
        sPu[(mh * 16 + row) * PSu + w] =
            g_xs[((size_t)(TIN - 1) * B_ + rowbase + mh * 16 + row) * 16 + w];
    }
    __syncthreads();

    int pp = 0;
    for (int t = 0; t < TOUT; t++) {
        const u32* hbu = sHu + hp * (32 * HSu);
        const uint4* h0p = reinterpret_cast<const uint4*>(hbu + R0 * HSu + tg * 8);
        const uint4* h1p = reinterpret_cast<const uint4*>(hbu + R1 * HSu + tg * 8);
        const uint4 v0a = h0p[0], v0b = h0p[1], v1a = h1p[0], v1b = h1p[1];
        u32 a0[4], a1[4], a2[4], a3[4];
        AFRAG_FROM(v0a, v0b, v1a, v1b, a0, a1, a2, a3);

        const u32* pbu = sPu + pp * (32 * PSu);
        const uint4 pv0 = *reinterpret_cast<const uint4*>(pbu + R0 * PSu + tg * 4);
        const uint4 pv1 = *reinterpret_cast<const uint4*>(pbu + R1 * PSu + tg * 4);
        u32 x0[2], x1[2], x2[2], x3[2];
        x0[0]=pv0.x; x2[0]=pv0.y; x0[1]=pv0.z; x2[1]=pv0.w;
        x1[0]=pv1.x; x3[0]=pv1.y; x1[1]=pv1.z; x3[1]=pv1.w;

        float accW[6][4], accP[2][4];
#pragma unroll
        for (int s = 0; s < 2; s++)
#pragma unroll
            for (int j = 0; j < 4; j++) {
                const int c = s * 2 + (j & 1);
                accW[s][j]     = dbr[c];
                accW[2 + s][j] = dbz[c];
                accW[4 + s][j] = dnh[c];
                accP[s][j]     = dni[c];
            }
#pragma unroll
        for (int nt = 0; nt < 6; nt++) {
            float* A = accW[nt];
#pragma unroll
            for (int ks = 0; ks < 4; ks++)
                MMA(A, a0[ks], a1[ks], a2[ks], a3[ks], bh[nt][ks][0], bh[nt][ks][1]);
#pragma unroll
            for (int ks = 0; ks < 4; ks++)
                MMA(A, a0[ks], a1[ks], a2[ks], a3[ks], bw[nt][ks][0], bw[nt][ks][1]);
            float* T = (nt < 4) ? A : accP[nt - 4];
#pragma unroll
            for (int ks = 0; ks < 2; ks++) {
                const uint2 w = sWf[((wq * 6 + nt) * 2 + ks) * 32 + lane];
                MMA(T, x0[ks], x1[ks], x2[ks], x3[ks], w.x, w.y);
            }
        }

        u32* hwu = sHu + (hp ^ 1) * (32 * HSu);
#pragma unroll
        for (int rh = 0; rh < 2; rh++) {
#pragma unroll
            for (int s = 0; s < 2; s++) {
                const int e = rh * 4 + s * 2;
                const float rg0 = fsig(accW[s][2*rh]);
                const float rg1 = fsig(accW[s][2*rh+1]);
                const float z0  = fsig(accW[2+s][2*rh]);
                const float z1  = fsig(accW[2+s][2*rh+1]);
                const float n0  = tanhap(fmaf(rg0, accW[4+s][2*rh],   accP[s][2*rh]));
                const float n1  = tanhap(fmaf(rg1, accW[4+s][2*rh+1], accP[s][2*rh+1]));
                h[e]   = n0 + z0 * (h[e]   - n0);
                h[e+1] = n1 + z1 * (h[e+1] - n1);
            }
        }
#pragma unroll
        for (int rh = 0; rh < 2; rh++) {
            const u32 p0 = packh2(h[rh*4+0], h[rh*4+1]);
            const u32 p1 = packh2(h[rh*4+2], h[rh*4+3]);
            const int row = rh ? R1 : R0;
            *reinterpret_cast<u64*>(&hwu[row * HSu + tg * 8 + 2 * wq]) =
                ((u64)p1 << 32) | p0;
        }
        asm volatile("bar.sync %0, %1;" :: "r"(barid), "r"(128) : "memory");

        // projection from NEW h
        {
            const u32* hnu = sHu + (hp ^ 1) * (32 * HSu);
            const uint4* n0p = reinterpret_cast<const uint4*>(hnu + R0 * HSu + tg * 8);
            const uint4* n1p = reinterpret_cast<const uint4*>(hnu + R1 * HSu + tg * 8);
            const uint4 w0a = n0p[0], w0b = n0p[1], w1a = n1p[0], w1b = n1p[1];
            u32 n0[4], n1[4], n2[4], n3[4];
            AFRAG_FROM(w0a, w0b, w1a, w1b, n0, n1, n2, n3);
            float pacc[4] = {0.f, 0.f, 0.f, 0.f};
#pragma unroll
            for (int ks = 0; ks < 4; ks++) {
                const uint4 w = sPf[(wq * 4 + ks) * 32 + lane];
                MMA(pacc, n0[ks], n1[ks], n2[ks], n3[ks], w.x, w.y);
                MMA(pacc, n0[ks], n1[ks], n2[ks], n3[ks], w.z, w.w);
            }
            const float p00 = pacc[0] + pb0, p01 = pacc[1] + pb1;
            const float p10 = pacc[2] + pb0, p11 = pacc[3] + pb1;
            *reinterpret_cast<float2*>(&out[((size_t)(rowbase + R0) * TOUT + t) * C_ + pcol]) = make_float2(p00, p01);
            *reinterpret_cast<float2*>(&out[((size_t)(rowbase + R1) * TOUT + t) * C_ + pcol]) = make_float2(p10, p11);
            u32* pnu = sPu + (pp ^ 1) * (32 * PSu);
            pnu[R0 * PSu + tg * 4 + wq] = packh2(p00, p01);
            pnu[R1 * PSu + tg * 4 + wq] = packh2(p10, p11);
        }
        asm volatile("bar.sync %0, %1;" :: "r"(barid), "r"(128) : "memory");
        hp ^= 1; pp ^= 1;
    }
}

// ============================ launch ============================
extern "C" void kernel_launch(void* const* d_in, const int* in_sizes, int n_in,
                              void* d_out, int out_size)
{
    (void)in_sizes; (void)n_in; (void)out_size;
    const float* x    = (const float*)d_in[0];
    const float* eWih = (const float*)d_in[1];
    const float* eWhh = (const float*)d_in[2];
    const float* eBih = (const float*)d_in[3];
    const float* eBhh = (const float*)d_in[4];
    const float* dWih = (const float*)d_in[5];
    const float* dWhh = (const float*)d_in[6];
    const float* dBih = (const float*)d_in[7];
    const float* dBhh = (const float*)d_in[8];
    const float* pW   = (const float*)d_in[9];
    const float* pB   = (const float*)d_in[10];
    float* out = (float*)d_out;

    xsplit_kernel<<<(TIN * B_) / 256, 256>>>(x);

    cudaFuncSetAttribute(gru_fused,
                         cudaFuncAttributeMaxDynamicSharedMemorySize, SM_TOTAL);
    gru_fused<<<B_ / 32, 256, SM_TOTAL>>>(
        x, eWih, eWhh, eBih, eBhh, dWih, dWhh, dBih, dBhh, pW, pB, out);
}